// round 1
// baseline (speedup 1.0000x reference)
#include <cuda_runtime.h>

// Problem constants
#define NB 16
#define NN 256
#define ND 256

// Scratch (device globals — allocation-free, fully overwritten every launch)
__device__ float g_Y[NB * NN * ND];   // Y[b] = x @ M[b]
__device__ float g_xT[ND * NN];       // x transposed
__device__ float g_q[NB * NN];        // q[b,i] = x_i^T M_b x_i

// ---------------------------------------------------------------------------
// Transpose x (256x256) -> g_xT so GEMM2's B-tile loads are coalesced.
// ---------------------------------------------------------------------------
__global__ void k_transpose(const float* __restrict__ x) {
    __shared__ float tile[32][33];
    const int bx = blockIdx.x * 32, by = blockIdx.y * 32;
    const int tx = threadIdx.x, ty = threadIdx.y;
    #pragma unroll
    for (int r = ty; r < 32; r += 8)
        tile[r][tx] = x[(by + r) * ND + bx + tx];
    __syncthreads();
    #pragma unroll
    for (int r = ty; r < 32; r += 8)
        g_xT[(bx + r) * NN + by + tx] = tile[tx][r];
}

// ---------------------------------------------------------------------------
// Register-tiled SGEMM body: C(64x64 tile) = A(256xK) * B(Kx256), K=256.
// 256 threads, 4x4 micro-tile per thread, BK=16, smem padded to stride 68
// (keeps 16B alignment for float4 while reducing store bank conflicts).
// EPI=false: C = A*B (plain store).
// EPI=true : C = q[row] + q[col] - 2*(A*B)   (fused quadratic-form epilogue)
// ---------------------------------------------------------------------------
template <bool EPI>
__device__ __forceinline__ void gemm_body(const float* __restrict__ A,
                                          const float* __restrict__ B,
                                          float* __restrict__ C,
                                          const float* __restrict__ q) {
    const int row0 = blockIdx.y * 64;
    const int col0 = blockIdx.x * 64;

    __shared__ float As[16][68];   // As[k][m]
    __shared__ float Bs[16][68];   // Bs[k][n]

    float acc[4][4] = {};

    const int tid = threadIdx.x;
    const int tx = tid & 15;       // n-direction (x4)
    const int ty = tid >> 4;       // m-direction (x4)

    // A-tile load mapping: 64 rows x 16 k -> one float4 per thread
    const int lr = tid >> 2;       // row within tile 0..63
    const int ls = tid & 3;        // float4 segment along k 0..3
    // B-tile load mapping: 16 k-rows x 64 cols -> one float4 per thread
    const int lk = tid >> 4;       // k within tile 0..15
    const int lc = tid & 15;       // float4 segment along n 0..15

    const float* aPtr = A + (row0 + lr) * 256 + ls * 4;
    const float* bPtr = B + lk * 256 + col0 + lc * 4;

    for (int k0 = 0; k0 < 256; k0 += 16) {
        const float4 av = *(const float4*)(aPtr + k0);
        const float4 bv = *(const float4*)(bPtr + (long)k0 * 256);

        __syncthreads();   // protect previous iteration's reads
        As[ls * 4 + 0][lr] = av.x;
        As[ls * 4 + 1][lr] = av.y;
        As[ls * 4 + 2][lr] = av.z;
        As[ls * 4 + 3][lr] = av.w;
        *(float4*)&Bs[lk][lc * 4] = bv;
        __syncthreads();

        #pragma unroll
        for (int kk = 0; kk < 16; kk++) {
            const float4 a  = *(const float4*)&As[kk][ty * 4];
            const float4 bb = *(const float4*)&Bs[kk][tx * 4];
            const float ar[4] = {a.x, a.y, a.z, a.w};
            const float br[4] = {bb.x, bb.y, bb.z, bb.w};
            #pragma unroll
            for (int i = 0; i < 4; i++)
                #pragma unroll
                for (int j = 0; j < 4; j++)
                    acc[i][j] += ar[i] * br[j];
        }
    }

    const int row = row0 + ty * 4;
    const int col = col0 + tx * 4;
    if (!EPI) {
        #pragma unroll
        for (int i = 0; i < 4; i++) {
            float4 v = make_float4(acc[i][0], acc[i][1], acc[i][2], acc[i][3]);
            *(float4*)&C[(row + i) * 256 + col] = v;
        }
    } else {
        float qj[4];
        #pragma unroll
        for (int j = 0; j < 4; j++) qj[j] = q[col + j];
        #pragma unroll
        for (int i = 0; i < 4; i++) {
            const float qi = q[row + i];
            float4 v = make_float4(qi + qj[0] - 2.0f * acc[i][0],
                                   qi + qj[1] - 2.0f * acc[i][1],
                                   qi + qj[2] - 2.0f * acc[i][2],
                                   qi + qj[3] - 2.0f * acc[i][3]);
            *(float4*)&C[(row + i) * 256 + col] = v;
        }
    }
}

// GEMM1: Y[b] = x @ M[b]
__global__ void __launch_bounds__(256) gemm1(const float* __restrict__ x,
                                             const float* __restrict__ M) {
    const int b = blockIdx.z;
    gemm_body<false>(x, M + (long)b * NN * ND, g_Y + (long)b * NN * ND, nullptr);
}

// GEMM2 + epilogue: out[b] = q_i + q_j - 2 * (Y[b] @ x^T)
__global__ void __launch_bounds__(256) gemm2(float* __restrict__ out) {
    const int b = blockIdx.z;
    gemm_body<true>(g_Y + (long)b * NN * ND, g_xT,
                    out + (long)b * NN * NN, g_q + b * NN);
}

// ---------------------------------------------------------------------------
// q[b,i] = dot(Y[b,i,:], x[i,:])  — one warp per (b,i) row.
// ---------------------------------------------------------------------------
__global__ void __launch_bounds__(256) kq(const float* __restrict__ x) {
    const int w = blockIdx.x * 8 + (threadIdx.x >> 5);   // 0 .. NB*NN-1
    const int lane = threadIdx.x & 31;
    const float* yr = g_Y + (long)w * 256;
    const float* xr = x + (long)(w & (NN - 1)) * 256;

    const float4 y0 = *(const float4*)(yr + lane * 4);
    const float4 x0 = *(const float4*)(xr + lane * 4);
    const float4 y1 = *(const float4*)(yr + 128 + lane * 4);
    const float4 x1 = *(const float4*)(xr + 128 + lane * 4);

    float s = y0.x * x0.x + y0.y * x0.y + y0.z * x0.z + y0.w * x0.w
            + y1.x * x1.x + y1.y * x1.y + y1.z * x1.z + y1.w * x1.w;

    #pragma unroll
    for (int off = 16; off; off >>= 1)
        s += __shfl_xor_sync(0xffffffffu, s, off);

    if (lane == 0) g_q[w] = s;
}

// ---------------------------------------------------------------------------
extern "C" void kernel_launch(void* const* d_in, const int* in_sizes, int n_in,
                              void* d_out, int out_size) {
    const float* x = (const float*)d_in[0];   // (256, 256) f32
    const float* M = (const float*)d_in[1];   // (16, 256, 256) f32
    float* out = (float*)d_out;               // (16, 256, 256) f32

    (void)in_sizes; (void)n_in; (void)out_size;

    k_transpose<<<dim3(8, 8), dim3(32, 8)>>>(x);
    gemm1<<<dim3(4, 4, NB), 256>>>(x, M);
    kq<<<NB * NN / 8, 256>>>(x);
    gemm2<<<dim3(4, 4, NB), 256>>>(out);
}

// round 4
// speedup vs baseline: 1.6000x; 1.6000x over previous
#include <cuda_runtime.h>
#include <cuda_bf16.h>
#include <stdint.h>

// ---------------------------------------------------------------------------
// out[b,i,j] = (x_i - x_j)^T M_b (x_i - x_j) = q_i + q_j - 2*G[b,i,j]
//   G = x M_b x^T,  q_i = G_ii.   B=16, N=D=256, fp32.
// Two 256^3 GEMM passes per batch on mma.sync (bf16 hi/lo split, fp32 accum).
// M symmetric  =>  B^T operand rows == M rows (no transpose anywhere).
// ---------------------------------------------------------------------------

// Global scratch (allocation-free)
__device__ __align__(16) unsigned short g_Xh[256 * 256];
__device__ __align__(16) unsigned short g_Xl[256 * 256];
__device__ __align__(16) unsigned short g_Mh[16 * 256 * 256];
__device__ __align__(16) unsigned short g_Ml[16 * 256 * 256];
__device__ __align__(16) unsigned short g_Yh[16 * 256 * 256];
__device__ __align__(16) unsigned short g_Yl[16 * 256 * 256];
__device__ float g_q[16 * 256];

__device__ __forceinline__ uint32_t smem_u32(const void* p) {
    uint32_t a;
    asm("{ .reg .u64 t; cvta.to.shared.u64 t, %1; cvt.u32.u64 %0, t; }"
        : "=r"(a) : "l"(p));
    return a;
}

__device__ __forceinline__ void cp16(uint32_t dst, const void* src) {
    asm volatile("cp.async.cg.shared.global [%0], [%1], 16;"
                 :: "r"(dst), "l"(src) : "memory");
}
#define CP_COMMIT() asm volatile("cp.async.commit_group;" ::: "memory")
template <int N>
__device__ __forceinline__ void cp_wait() {
    asm volatile("cp.async.wait_group %0;" :: "n"(N) : "memory");
}

__device__ __forceinline__ void ldm_x4(uint32_t* r, uint32_t addr) {
    asm volatile("ldmatrix.sync.aligned.m8n8.x4.shared.b16 {%0,%1,%2,%3}, [%4];"
                 : "=r"(r[0]), "=r"(r[1]), "=r"(r[2]), "=r"(r[3]) : "r"(addr));
}
__device__ __forceinline__ void mma_bf16(float* d, const uint32_t* a,
                                         uint32_t b0, uint32_t b1) {
    asm volatile(
        "mma.sync.aligned.m16n8k16.row.col.f32.bf16.bf16.f32 "
        "{%0,%1,%2,%3}, {%4,%5,%6,%7}, {%8,%9}, {%0,%1,%2,%3};"
        : "+f"(d[0]), "+f"(d[1]), "+f"(d[2]), "+f"(d[3])
        : "r"(a[0]), "r"(a[1]), "r"(a[2]), "r"(a[3]), "r"(b0), "r"(b1));
}

// ---------------------------------------------------------------------------
// Convert: x, M -> row-major bf16 hi/lo splits. One thread per float4.
// ---------------------------------------------------------------------------
__global__ void __launch_bounds__(256) k_convert(const float* __restrict__ x,
                                                 const float* __restrict__ M) {
    const int idx = blockIdx.x * 256 + threadIdx.x;        // float4 index
    const float4* src;
    unsigned short *dh, *dl;
    if (idx < 16 * 65536 / 4) {
        src = (const float4*)M + idx;
        dh = g_Mh + idx * 4;  dl = g_Ml + idx * 4;
    } else {
        const int t = idx - 16 * 65536 / 4;
        if (t >= 65536 / 4) return;
        src = (const float4*)x + t;
        dh = g_Xh + t * 4;  dl = g_Xl + t * 4;
    }
    const float4 v = *src;
    const float vv[4] = {v.x, v.y, v.z, v.w};
    unsigned short hs[4], ls[4];
    #pragma unroll
    for (int i = 0; i < 4; i++) {
        const __nv_bfloat16 h = __float2bfloat16(vv[i]);
        const __nv_bfloat16 l = __float2bfloat16(vv[i] - __bfloat162float(h));
        hs[i] = __bfloat16_as_ushort(h);
        ls[i] = __bfloat16_as_ushort(l);
    }
    uint2 ph, pl;
    ph.x = (uint32_t)hs[0] | ((uint32_t)hs[1] << 16);
    ph.y = (uint32_t)hs[2] | ((uint32_t)hs[3] << 16);
    pl.x = (uint32_t)ls[0] | ((uint32_t)ls[1] << 16);
    pl.y = (uint32_t)ls[2] | ((uint32_t)ls[3] << 16);
    *(uint2*)dh = ph;
    *(uint2*)dl = pl;
}

// ---------------------------------------------------------------------------
// GEMM: block tile 64(M) x 128(N), 4 warps (warp tile 64x32), BK=32, 3-stage
// cp.async pipeline.  D += Ah*Bh + Ah*Bl + Al*Bh  (fp32 accum in registers).
// Smem per stage (24576B): Ah@0 (64x32 bf16), Al@4096, Bh@8192 (128x32), Bl@16384.
// Row = 64B = 4 x 16B chunks, chunk swizzle c ^ ((row>>1)&3) => conflict-free
// ldmatrix and conflict-free cp.async stores.
// B operand (Bt stored [n,k] row-major) loads with NORMAL ldmatrix — for
// mma .row.col, the col-major k16xn8 B IS the row-major [n,k] fragment layout.
// PHASE 1: A=x, Bt=M_b rows; epilogue -> Yh/Yl.
// PHASE 2: A=Y_b, Bt=x rows; epilogue -> out = q_i + q_j - 2*acc.
// ---------------------------------------------------------------------------
#define STAGE_B 24576
#define QS_OFF  (3 * STAGE_B)
#define SMEM_B  (QS_OFF + 1024)

template <int PHASE>
__global__ void __launch_bounds__(128) k_gemm(float* __restrict__ out) {
    extern __shared__ __align__(128) unsigned char smem[];
    const uint32_t sb = smem_u32(smem);
    const int tid = threadIdx.x;
    const int wid = tid >> 5, l = tid & 31;
    const int b   = blockIdx.z;
    const int bm0 = blockIdx.y * 64;
    const int bn0 = blockIdx.x * 128;

    const unsigned short *Ah, *Al, *Bh, *Bl;
    if (PHASE == 1) {
        Ah = g_Xh + bm0 * 256;             Al = g_Xl + bm0 * 256;
        Bh = g_Mh + b * 65536 + bn0 * 256; Bl = g_Ml + b * 65536 + bn0 * 256;
    } else {
        Ah = g_Yh + b * 65536 + bm0 * 256; Al = g_Yl + b * 65536 + bm0 * 256;
        Bh = g_Xh + bn0 * 256;             Bl = g_Xl + bn0 * 256;
    }

    if (PHASE == 2) {
        float* qs = (float*)(smem + QS_OFF);
        qs[tid]       = g_q[b * 256 + tid];
        qs[tid + 128] = g_q[b * 256 + tid + 128];
    }

    // cp.async issue of one BK=32 chunk (kc = chunk index 0..7) into stage s
    auto issue = [&](int kc, int s) {
        const uint32_t st = sb + s * STAGE_B;
        const int k0 = kc * 32;
        // A: 64 rows x 4 chunks = 256; thread does 2 (row = tid>>1)
        {
            const int row = tid >> 1;
            #pragma unroll
            for (int j = 0; j < 2; j++) {
                const int c = (tid & 1) * 2 + j;
                const uint32_t d = st + row * 64 + ((c ^ ((row >> 1) & 3)) << 4);
                cp16(d,        Ah + row * 256 + k0 + c * 8);
                cp16(d + 4096, Al + row * 256 + k0 + c * 8);
            }
        }
        // B: 128 rows x 4 chunks; thread does one row's 4 chunks
        {
            const int row = tid;
            #pragma unroll
            for (int c = 0; c < 4; c++) {
                const uint32_t d = st + 8192 + row * 64 + ((c ^ ((row >> 1) & 3)) << 4);
                cp16(d,        Bh + row * 256 + k0 + c * 8);
                cp16(d + 8192, Bl + row * 256 + k0 + c * 8);
            }
        }
    };

    float acc[4][4][4] = {};   // [mt][n8][reg]

    issue(0, 0); CP_COMMIT();
    issue(1, 1); CP_COMMIT();

    // ldmatrix lane-address components (row part), constant across k
    const int rA = (l & 15);                    // A: row within m16 tile
    const int hA = (l >> 4);                    // A: k8-half select
    const int rB = ((l >> 4) << 3) + (l & 7);   // B: n-row within n16 group
    const int hB = ((l >> 3) & 1);              // B: k8-half select

    for (int i = 0; i < 8; i++) {
        cp_wait<1>();
        __syncthreads();
        if (i + 2 < 8) issue(i + 2, (i + 2) % 3);
        CP_COMMIT();

        const uint32_t st = sb + (i % 3) * STAGE_B;
        #pragma unroll
        for (int ks = 0; ks < 2; ks++) {
            uint32_t ah[4][4], al[4][4], bh[2][4], bl[2][4];
            #pragma unroll
            for (int mt = 0; mt < 4; mt++) {
                const int row = mt * 16 + rA;
                const int c = (ks * 2 + hA) ^ ((row >> 1) & 3);
                const uint32_t a = st + row * 64 + (c << 4);
                ldm_x4(ah[mt], a);
                ldm_x4(al[mt], a + 4096);
            }
            #pragma unroll
            for (int nt = 0; nt < 2; nt++) {
                const int row = wid * 32 + nt * 16 + rB;
                const int c = (ks * 2 + hB) ^ ((row >> 1) & 3);
                const uint32_t a = st + 8192 + row * 64 + (c << 4);
                ldm_x4(bh[nt], a);          // NORMAL ldmatrix (row.col B)
                ldm_x4(bl[nt], a + 8192);
            }
            #pragma unroll
            for (int mt = 0; mt < 4; mt++)
                #pragma unroll
                for (int j = 0; j < 4; j++) {
                    const int g = j >> 1, o = (j & 1) * 2;
                    mma_bf16(acc[mt][j], ah[mt], bh[g][o], bh[g][o + 1]);
                    mma_bf16(acc[mt][j], ah[mt], bl[g][o], bl[g][o + 1]);
                    mma_bf16(acc[mt][j], al[mt], bh[g][o], bh[g][o + 1]);
                }
        }
    }

    // ------------------------------------------------------------------ epi
    const int lr = l >> 2;          // 0..7
    const int lc = (l & 3) * 2;     // 0,2,4,6

    if (PHASE == 1) {
        unsigned short* yh = g_Yh + b * 65536;
        unsigned short* yl = g_Yl + b * 65536;
        #pragma unroll
        for (int mt = 0; mt < 4; mt++)
            #pragma unroll
            for (int j = 0; j < 4; j++) {
                const int col = bn0 + wid * 32 + j * 8 + lc;
                #pragma unroll
                for (int half = 0; half < 2; half++) {
                    const int row = bm0 + mt * 16 + lr + half * 8;
                    const float v0 = acc[mt][j][half * 2 + 0];
                    const float v1 = acc[mt][j][half * 2 + 1];
                    const __nv_bfloat16 h0 = __float2bfloat16(v0);
                    const __nv_bfloat16 h1 = __float2bfloat16(v1);
                    const __nv_bfloat16 e0 = __float2bfloat16(v0 - __bfloat162float(h0));
                    const __nv_bfloat16 e1 = __float2bfloat16(v1 - __bfloat162float(h1));
                    const uint32_t ph = (uint32_t)__bfloat16_as_ushort(h0)
                                      | ((uint32_t)__bfloat16_as_ushort(h1) << 16);
                    const uint32_t pl = (uint32_t)__bfloat16_as_ushort(e0)
                                      | ((uint32_t)__bfloat16_as_ushort(e1) << 16);
                    *(uint32_t*)(yh + row * 256 + col) = ph;
                    *(uint32_t*)(yl + row * 256 + col) = pl;
                }
            }
    } else {
        const float* qs = (const float*)(smem + QS_OFF);
        float* ob = out + ((size_t)b << 16);
        #pragma unroll
        for (int mt = 0; mt < 4; mt++)
            #pragma unroll
            for (int j = 0; j < 4; j++) {
                const int col = bn0 + wid * 32 + j * 8 + lc;
                const float qj0 = qs[col], qj1 = qs[col + 1];
                #pragma unroll
                for (int half = 0; half < 2; half++) {
                    const int row = bm0 + mt * 16 + lr + half * 8;
                    const float qi = qs[row];
                    float2 v;
                    v.x = qi + qj0 - 2.0f * acc[mt][j][half * 2 + 0];
                    v.y = qi + qj1 - 2.0f * acc[mt][j][half * 2 + 1];
                    *(float2*)(ob + row * 256 + col) = v;
                }
            }
    }
}

// ---------------------------------------------------------------------------
// q[b,i] = dot(Y[b,i,:], x[i,:])  (Y reconstructed hi+lo) — one warp per row.
// ---------------------------------------------------------------------------
__global__ void __launch_bounds__(256) kq(const float* __restrict__ x) {
    const int w = blockIdx.x * 8 + (threadIdx.x >> 5);   // 0..4095
    const int lane = threadIdx.x & 31;
    const int b = w >> 8, i = w & 255;
    const unsigned short* yh = g_Yh + b * 65536 + i * 256;
    const unsigned short* yl = g_Yl + b * 65536 + i * 256;
    const float* xr = x + i * 256;

    float s = 0.0f;
    #pragma unroll
    for (int seg = 0; seg < 2; seg++) {
        const int k0 = seg * 128 + lane * 4;
        const uint2 ph = *(const uint2*)(yh + k0);
        const uint2 pl = *(const uint2*)(yl + k0);
        const float4 xv = *(const float4*)(xr + k0);
        const float y0 = __bfloat162float(__ushort_as_bfloat16((unsigned short)(ph.x & 0xffff)))
                       + __bfloat162float(__ushort_as_bfloat16((unsigned short)(pl.x & 0xffff)));
        const float y1 = __bfloat162float(__ushort_as_bfloat16((unsigned short)(ph.x >> 16)))
                       + __bfloat162float(__ushort_as_bfloat16((unsigned short)(pl.x >> 16)));
        const float y2 = __bfloat162float(__ushort_as_bfloat16((unsigned short)(ph.y & 0xffff)))
                       + __bfloat162float(__ushort_as_bfloat16((unsigned short)(pl.y & 0xffff)));
        const float y3 = __bfloat162float(__ushort_as_bfloat16((unsigned short)(ph.y >> 16)))
                       + __bfloat162float(__ushort_as_bfloat16((unsigned short)(pl.y >> 16)));
        s += y0 * xv.x + y1 * xv.y + y2 * xv.z + y3 * xv.w;
    }
    #pragma unroll
    for (int off = 16; off; off >>= 1)
        s += __shfl_xor_sync(0xffffffffu, s, off);
    if (lane == 0) g_q[w] = s;
}

// ---------------------------------------------------------------------------
extern "C" void kernel_launch(void* const* d_in, const int* in_sizes, int n_in,
                              void* d_out, int out_size) {
    const float* x = (const float*)d_in[0];   // (256, 256) f32
    const float* M = (const float*)d_in[1];   // (16, 256, 256) f32
    float* out = (float*)d_out;               // (16, 256, 256) f32
    (void)in_sizes; (void)n_in; (void)out_size;

    (void)cudaFuncSetAttribute(k_gemm<1>, cudaFuncAttributeMaxDynamicSharedMemorySize, SMEM_B);
    (void)cudaFuncSetAttribute(k_gemm<2>, cudaFuncAttributeMaxDynamicSharedMemorySize, SMEM_B);

    k_convert<<<1088, 256>>>(x, M);
    k_gemm<1><<<dim3(2, 4, 16), 128, SMEM_B>>>(nullptr);
    kq<<<512, 256>>>(x);
    k_gemm<2><<<dim3(2, 4, 16), 128, SMEM_B>>>(out);
}

// round 5
// speedup vs baseline: 1.8439x; 1.1525x over previous
#include <cuda_runtime.h>
#include <cuda_bf16.h>
#include <stdint.h>

// ---------------------------------------------------------------------------
// out[b,i,j] = (x_i - x_j)^T M_b (x_i - x_j) = q_i + q_j - 2*G[b,i,j]
//   G = x M_b x^T,  q_i = G_ii.   B=16, N=D=256, fp32.
// Two 256^3 GEMM passes per batch on mma.sync (bf16 hi/lo split, fp32 accum).
// M symmetric  =>  B^T operand rows == M rows (no transpose anywhere).
// R5: 64x64 tiles (grid 256 => ~2 blocks/SM), q fused into pass-1 epilogue.
// ---------------------------------------------------------------------------

__device__ __align__(16) unsigned short g_Xh[256 * 256];
__device__ __align__(16) unsigned short g_Xl[256 * 256];
__device__ __align__(16) unsigned short g_Mh[16 * 256 * 256];
__device__ __align__(16) unsigned short g_Ml[16 * 256 * 256];
__device__ __align__(16) unsigned short g_Yh[16 * 256 * 256];
__device__ __align__(16) unsigned short g_Yl[16 * 256 * 256];
__device__ float g_q[16 * 256];

__device__ __forceinline__ uint32_t smem_u32(const void* p) {
    uint32_t a;
    asm("{ .reg .u64 t; cvta.to.shared.u64 t, %1; cvt.u32.u64 %0, t; }"
        : "=r"(a) : "l"(p));
    return a;
}

__device__ __forceinline__ void cp16(uint32_t dst, const void* src) {
    asm volatile("cp.async.cg.shared.global [%0], [%1], 16;"
                 :: "r"(dst), "l"(src) : "memory");
}
#define CP_COMMIT() asm volatile("cp.async.commit_group;" ::: "memory")
template <int N>
__device__ __forceinline__ void cp_wait() {
    asm volatile("cp.async.wait_group %0;" :: "n"(N) : "memory");
}

__device__ __forceinline__ void ldm_x4(uint32_t* r, uint32_t addr) {
    asm volatile("ldmatrix.sync.aligned.m8n8.x4.shared.b16 {%0,%1,%2,%3}, [%4];"
                 : "=r"(r[0]), "=r"(r[1]), "=r"(r[2]), "=r"(r[3]) : "r"(addr));
}
__device__ __forceinline__ void mma_bf16(float* d, const uint32_t* a,
                                         uint32_t b0, uint32_t b1) {
    asm volatile(
        "mma.sync.aligned.m16n8k16.row.col.f32.bf16.bf16.f32 "
        "{%0,%1,%2,%3}, {%4,%5,%6,%7}, {%8,%9}, {%0,%1,%2,%3};"
        : "+f"(d[0]), "+f"(d[1]), "+f"(d[2]), "+f"(d[3])
        : "r"(a[0]), "r"(a[1]), "r"(a[2]), "r"(a[3]), "r"(b0), "r"(b1));
}

// ---------------------------------------------------------------------------
// Convert: x, M -> row-major bf16 hi/lo splits; also zero g_q.
// ---------------------------------------------------------------------------
__global__ void __launch_bounds__(256) k_convert(const float* __restrict__ x,
                                                 const float* __restrict__ M) {
    const int idx = blockIdx.x * 256 + threadIdx.x;        // float4 index
    if (idx < 16 * 256) g_q[idx] = 0.0f;

    const float4* src;
    unsigned short *dh, *dl;
    if (idx < 16 * 65536 / 4) {
        src = (const float4*)M + idx;
        dh = g_Mh + idx * 4;  dl = g_Ml + idx * 4;
    } else {
        const int t = idx - 16 * 65536 / 4;
        if (t >= 65536 / 4) return;
        src = (const float4*)x + t;
        dh = g_Xh + t * 4;  dl = g_Xl + t * 4;
    }
    const float4 v = *src;
    const float vv[4] = {v.x, v.y, v.z, v.w};
    unsigned short hs[4], ls[4];
    #pragma unroll
    for (int i = 0; i < 4; i++) {
        const __nv_bfloat16 h = __float2bfloat16(vv[i]);
        const __nv_bfloat16 l = __float2bfloat16(vv[i] - __bfloat162float(h));
        hs[i] = __bfloat16_as_ushort(h);
        ls[i] = __bfloat16_as_ushort(l);
    }
    uint2 ph, pl;
    ph.x = (uint32_t)hs[0] | ((uint32_t)hs[1] << 16);
    ph.y = (uint32_t)hs[2] | ((uint32_t)hs[3] << 16);
    pl.x = (uint32_t)ls[0] | ((uint32_t)ls[1] << 16);
    pl.y = (uint32_t)ls[2] | ((uint32_t)ls[3] << 16);
    *(uint2*)dh = ph;
    *(uint2*)dl = pl;
}

// ---------------------------------------------------------------------------
// GEMM: block tile 64x64, 4 warps (warp tile 32x32, warps 2x2), BK=32,
// 3-stage cp.async pipeline.  D += Ah*Bh + Ah*Bl + Al*Bh.
// Stage (16384B): Ah@0 (64x32 bf16, 64B rows), Al@4096, Bh@8192, Bl@12288.
// Chunk swizzle c ^ ((row>>1)&3) (16B chunks) — conflict-free both ways.
// PHASE 1: A=x, Bt=M_b rows; epilogue -> Yh/Yl + fused partial q (atomics).
// PHASE 2: A=Y_b, Bt=x rows; epilogue -> out = q_i + q_j - 2*acc.
// ---------------------------------------------------------------------------
#define STAGE_B 16384
#define QS_OFF  (3 * STAGE_B)
#define SMEM_B  (QS_OFF + 1024)

template <int PHASE>
__global__ void __launch_bounds__(128) k_gemm(const float* __restrict__ x,
                                              float* __restrict__ out) {
    extern __shared__ __align__(128) unsigned char smem[];
    const uint32_t sb = smem_u32(smem);
    const int tid = threadIdx.x;
    const int wid = tid >> 5, l = tid & 31;
    const int wm  = wid & 1, wn = wid >> 1;      // 2x2 warp grid
    const int b   = blockIdx.z;
    const int bm0 = blockIdx.y * 64;
    const int bn0 = blockIdx.x * 64;

    const unsigned short *Ah, *Al, *Bh, *Bl;
    if (PHASE == 1) {
        Ah = g_Xh + bm0 * 256;             Al = g_Xl + bm0 * 256;
        Bh = g_Mh + b * 65536 + bn0 * 256; Bl = g_Ml + b * 65536 + bn0 * 256;
    } else {
        Ah = g_Yh + b * 65536 + bm0 * 256; Al = g_Yl + b * 65536 + bm0 * 256;
        Bh = g_Xh + bn0 * 256;             Bl = g_Xl + bn0 * 256;
    }

    if (PHASE == 2) {
        float* qs = (float*)(smem + QS_OFF);
        qs[tid]       = g_q[b * 256 + tid];
        qs[tid + 128] = g_q[b * 256 + tid + 128];
    }

    // one BK=32 chunk (kc 0..7) into stage s: 8 cp16 per thread
    auto issue = [&](int kc, int s) {
        const uint32_t st = sb + s * STAGE_B;
        const int k0 = kc * 32;
        const int row = tid >> 1;
        #pragma unroll
        for (int j = 0; j < 2; j++) {
            const int c = (tid & 1) * 2 + j;
            const uint32_t d = st + row * 64 + ((c ^ ((row >> 1) & 3)) << 4);
            cp16(d,         Ah + row * 256 + k0 + c * 8);
            cp16(d + 4096,  Al + row * 256 + k0 + c * 8);
            cp16(d + 8192,  Bh + row * 256 + k0 + c * 8);
            cp16(d + 12288, Bl + row * 256 + k0 + c * 8);
        }
    };

    float acc[2][4][4] = {};   // [mt][n8][reg]

    issue(0, 0); CP_COMMIT();
    issue(1, 1); CP_COMMIT();

    const int rA = (l & 15);                    // A: row within m16 tile
    const int hA = (l >> 4);                    // A: k8-half select
    const int rB = ((l >> 4) << 3) + (l & 7);   // B: n-row within n16 group
    const int hB = ((l >> 3) & 1);              // B: k8-half select

    for (int i = 0; i < 8; i++) {
        cp_wait<1>();
        __syncthreads();
        if (i + 2 < 8) issue(i + 2, (i + 2) % 3);
        CP_COMMIT();

        const uint32_t st = sb + (i % 3) * STAGE_B;
        #pragma unroll
        for (int ks = 0; ks < 2; ks++) {
            uint32_t ah[2][4], al[2][4], bh[2][4], bl[2][4];
            #pragma unroll
            for (int mt = 0; mt < 2; mt++) {
                const int row = wm * 32 + mt * 16 + rA;
                const int c = (ks * 2 + hA) ^ ((row >> 1) & 3);
                const uint32_t a = st + row * 64 + (c << 4);
                ldm_x4(ah[mt], a);
                ldm_x4(al[mt], a + 4096);
            }
            #pragma unroll
            for (int nt = 0; nt < 2; nt++) {
                const int row = wn * 32 + nt * 16 + rB;
                const int c = (ks * 2 + hB) ^ ((row >> 1) & 3);
                const uint32_t a = st + 8192 + row * 64 + (c << 4);
                ldm_x4(bh[nt], a);
                ldm_x4(bl[nt], a + 4096);
            }
            #pragma unroll
            for (int mt = 0; mt < 2; mt++)
                #pragma unroll
                for (int j = 0; j < 4; j++) {
                    const int g = j >> 1, o = (j & 1) * 2;
                    mma_bf16(acc[mt][j], ah[mt], bh[g][o], bh[g][o + 1]);
                    mma_bf16(acc[mt][j], ah[mt], bl[g][o], bl[g][o + 1]);
                    mma_bf16(acc[mt][j], al[mt], bh[g][o], bh[g][o + 1]);
                }
        }
    }

    // ------------------------------------------------------------------ epi
    const int lr = l >> 2;          // 0..7
    const int lc = (l & 3) * 2;     // 0,2,4,6

    if (PHASE == 1) {
        unsigned short* yh = g_Yh + b * 65536;
        unsigned short* yl = g_Yl + b * 65536;
        #pragma unroll
        for (int mt = 0; mt < 2; mt++)
            #pragma unroll
            for (int half = 0; half < 2; half++) {
                const int row = bm0 + wm * 32 + mt * 16 + lr + half * 8;
                float qpart = 0.0f;
                #pragma unroll
                for (int j = 0; j < 4; j++) {
                    const int col = bn0 + wn * 32 + j * 8 + lc;
                    const float v0 = acc[mt][j][half * 2 + 0];
                    const float v1 = acc[mt][j][half * 2 + 1];
                    const float2 xv = *(const float2*)(x + row * 256 + col);
                    qpart += v0 * xv.x + v1 * xv.y;
                    const __nv_bfloat16 h0 = __float2bfloat16(v0);
                    const __nv_bfloat16 h1 = __float2bfloat16(v1);
                    const __nv_bfloat16 e0 = __float2bfloat16(v0 - __bfloat162float(h0));
                    const __nv_bfloat16 e1 = __float2bfloat16(v1 - __bfloat162float(h1));
                    const uint32_t ph = (uint32_t)__bfloat16_as_ushort(h0)
                                      | ((uint32_t)__bfloat16_as_ushort(h1) << 16);
                    const uint32_t pl = (uint32_t)__bfloat16_as_ushort(e0)
                                      | ((uint32_t)__bfloat16_as_ushort(e1) << 16);
                    *(uint32_t*)(yh + row * 256 + col) = ph;
                    *(uint32_t*)(yl + row * 256 + col) = pl;
                }
                // quad reduce (lanes sharing lr) then one atomic per row/warp
                qpart += __shfl_xor_sync(0xffffffffu, qpart, 1);
                qpart += __shfl_xor_sync(0xffffffffu, qpart, 2);
                if ((l & 3) == 0) atomicAdd(g_q + b * 256 + row, qpart);
            }
    } else {
        const float* qs = (const float*)(smem + QS_OFF);
        float* ob = out + ((size_t)b << 16);
        #pragma unroll
        for (int mt = 0; mt < 2; mt++)
            #pragma unroll
            for (int j = 0; j < 4; j++) {
                const int col = bn0 + wn * 32 + j * 8 + lc;
                const float qj0 = qs[col], qj1 = qs[col + 1];
                #pragma unroll
                for (int half = 0; half < 2; half++) {
                    const int row = bm0 + wm * 32 + mt * 16 + lr + half * 8;
                    const float qi = qs[row];
                    float2 v;
                    v.x = qi + qj0 - 2.0f * acc[mt][j][half * 2 + 0];
                    v.y = qi + qj1 - 2.0f * acc[mt][j][half * 2 + 1];
                    *(float2*)(ob + row * 256 + col) = v;
                }
            }
    }
}

// ---------------------------------------------------------------------------
extern "C" void kernel_launch(void* const* d_in, const int* in_sizes, int n_in,
                              void* d_out, int out_size) {
    const float* x = (const float*)d_in[0];   // (256, 256) f32
    const float* M = (const float*)d_in[1];   // (16, 256, 256) f32
    float* out = (float*)d_out;               // (16, 256, 256) f32
    (void)in_sizes; (void)n_in; (void)out_size;

    (void)cudaFuncSetAttribute(k_gemm<1>, cudaFuncAttributeMaxDynamicSharedMemorySize, SMEM_B);
    (void)cudaFuncSetAttribute(k_gemm<2>, cudaFuncAttributeMaxDynamicSharedMemorySize, SMEM_B);

    k_convert<<<1088, 256>>>(x, M);
    k_gemm<1><<<dim3(4, 4, 16), 128, SMEM_B>>>(x, nullptr);
    k_gemm<2><<<dim3(4, 4, 16), 128, SMEM_B>>>(x, out);
}